// round 3
// baseline (speedup 1.0000x reference)
#include <cuda_runtime.h>
#include <cstdint>

#define B_SZ   1024
#define T_SZ   16
#define IN_DIM 2048
#define DIM    1024
#define NACT   64

// ---------------- scratch (no allocations allowed) ----------------
__device__ float g_pavg[B_SZ * IN_DIM];     // 8 MB (tf32-rounded)
__device__ float g_eavg[B_SZ * IN_DIM];     // 8 MB (tf32-rounded)
__device__ float g_wpr[DIM * IN_DIM];       // 8 MB tf32-rounded Wp
__device__ float g_wer[DIM * IN_DIM];       // 8 MB tf32-rounded We
__device__ float g_pembed[B_SZ * DIM];      // 4 MB (tf32-rounded)
__device__ int   g_counts[NACT];
__device__ int   g_cursor[NACT];            // group END after group_k
__device__ int   g_order[B_SZ];

// ---------------- helpers ----------------
__device__ __forceinline__ uint32_t f2tf32(float x) {
    uint32_t r;
    asm("cvt.rna.tf32.f32 %0, %1;" : "=r"(r) : "f"(x));
    return r;
}
__device__ __forceinline__ float f2tf32f(float x) { return __uint_as_float(f2tf32(x)); }

__device__ __forceinline__ void mma_tf32(float c[4], const uint32_t a[4], const uint32_t b[2]) {
    asm volatile(
        "mma.sync.aligned.m16n8k8.row.col.f32.tf32.tf32.f32 "
        "{%0,%1,%2,%3}, {%4,%5,%6,%7}, {%8,%9}, {%0,%1,%2,%3};"
        : "+f"(c[0]), "+f"(c[1]), "+f"(c[2]), "+f"(c[3])
        : "r"(a[0]), "r"(a[1]), "r"(a[2]), "r"(a[3]), "r"(b[0]), "r"(b[1]));
}

__device__ __forceinline__ void cpa16(float* dst, const float* src, uint32_t src_sz) {
    uint32_t d = (uint32_t)__cvta_generic_to_shared(dst);
    asm volatile("cp.async.ca.shared.global [%0], [%1], 16, %2;"
                 :: "r"(d), "l"(src), "r"(src_sz));
}
__device__ __forceinline__ void cpa_commit() { asm volatile("cp.async.commit_group;"); }
__device__ __forceinline__ void cpa_wait0()  { asm volatile("cp.async.wait_group 0;"); }
__device__ __forceinline__ void cpa_wait2()  { asm volatile("cp.async.wait_group 2;"); }

// ---------------- fused grouping: count + scan + scatter in ONE block ----------------
__global__ void group_k(const int* __restrict__ act) {
    __shared__ int s_cnt[NACT];
    __shared__ int s_base[NACT];
    const int tid = threadIdx.x;           // 1024 threads, one per batch
    if (tid < NACT) s_cnt[tid] = 0;
    __syncthreads();
    const int a = act[tid];
    atomicAdd(&s_cnt[a], 1);
    __syncthreads();
    if (tid == 0) {
        int run = 0;
        for (int i = 0; i < NACT; i++) { int c = s_cnt[i]; s_base[i] = run; run += c; }
    }
    __syncthreads();
    int pos = atomicAdd(&s_base[a], 1);
    g_order[pos] = tid;
    __syncthreads();
    if (tid < NACT) {
        g_counts[tid] = s_cnt[tid];
        g_cursor[tid] = s_base[tid];       // = group end
    }
}

// ---------------- time-mean (float4, tf32-rounded at store) ----------------
__global__ void mean_kernel(const float* __restrict__ pre, const float* __restrict__ eff) {
    const int idx = blockIdx.x * 256 + threadIdx.x;   // over B*IN/4
    const float4* src = (const float4*)(blockIdx.y ? eff : pre);
    float4*       dst = (float4*)(blockIdx.y ? g_eavg : g_pavg);
    const int b  = idx >> 9;               // / (IN_DIM/4)
    const int k4 = idx & 511;
    const float4* p = src + (size_t)b * T_SZ * (IN_DIM / 4) + k4;
    float4 s = make_float4(0.f, 0.f, 0.f, 0.f);
#pragma unroll
    for (int t = 0; t < T_SZ; t++) {
        float4 v = p[(size_t)t * (IN_DIM / 4)];
        s.x += v.x; s.y += v.y; s.z += v.z; s.w += v.w;
    }
    const float inv = 1.0f / T_SZ;
    dst[idx] = make_float4(f2tf32f(s.x * inv), f2tf32f(s.y * inv),
                           f2tf32f(s.z * inv), f2tf32f(s.w * inv));
}

// ---------------- pre-round Wp/We to tf32 ----------------
__global__ void wconv_k(const float* __restrict__ Wp, const float* __restrict__ We) {
    const int half = DIM * IN_DIM / 4;     // 524288 float4
    int idx = blockIdx.x * 256 + threadIdx.x;
    const float4* src;
    float4* dst;
    int j;
    if (idx < half) { src = (const float4*)Wp; dst = (float4*)g_wpr; j = idx; }
    else            { src = (const float4*)We; dst = (float4*)g_wer; j = idx - half; }
    float4 v = src[j];
    dst[j] = make_float4(f2tf32f(v.x), f2tf32f(v.y), f2tf32f(v.z), f2tf32f(v.w));
}

// ---------------- embedding GEMM: C[1024x1024] = A[1024x2048] @ W^T + bias ----------------
// 128x128 tile, BK=32, cp.async double-buffered, 8 warps (2M x 4N), warp tile 64x32
// All operands pre-rounded to tf32 -> no cvt in the hot loop.
#define G1_BM 128
#define G1_BN 128
#define G1_BK 32
#define SPAD  36
#define G1_SMEM (4 * 128 * SPAD * 4)   // 2 bufs * (As 128x36 + Bs 128x36) floats

__global__ __launch_bounds__(256) void embed_gemm(
    const float* __restrict__ bp, const float* __restrict__ be,
    float* __restrict__ out_e)
{
    extern __shared__ float sm[];
    float* AsBase = sm;                       // [2][128][36]
    float* BsBase = sm + 2 * 128 * SPAD;      // [2][128][36]

    const float *A, *W, *bias;
    float* out;
    bool roundOut;
    if (blockIdx.z == 0) { A = g_pavg; W = g_wpr; bias = bp; out = g_pembed; roundOut = true;  }
    else                 { A = g_eavg; W = g_wer; bias = be; out = out_e;    roundOut = false; }

    const int m0 = blockIdx.y * G1_BM;
    const int n0 = blockIdx.x * G1_BN;
    const int tid  = threadIdx.x;
    const int lane = tid & 31;
    const int warp = tid >> 5;
    const int wm = (warp >> 2) * 64;   // 2 warp-rows over 128 M
    const int wn = (warp & 3) * 32;    // 4 warp-cols over 128 N

    const int lr = tid >> 3;
    const int lc = (tid & 7) * 4;

    float acc[4][4][4];
#pragma unroll
    for (int i = 0; i < 4; i++)
#pragma unroll
        for (int j = 0; j < 4; j++)
#pragma unroll
            for (int r = 0; r < 4; r++) acc[i][j][r] = 0.f;

    // prologue: stage 0
    {
#pragma unroll
        for (int i = 0; i < 4; i++) {
            int r = lr + i * 32;
            cpa16(&AsBase[r * SPAD + lc], A + (size_t)(m0 + r) * IN_DIM + lc, 16);
            cpa16(&BsBase[r * SPAD + lc], W + (size_t)(n0 + r) * IN_DIM + lc, 16);
        }
        cpa_commit();
    }

    const int NITER = IN_DIM / G1_BK;  // 64
    for (int it = 0; it < NITER; ++it) {
        cpa_wait0();
        __syncthreads();

        if (it + 1 < NITER) {
            const int k0 = (it + 1) * G1_BK;
            float* Ab = AsBase + ((it + 1) & 1) * 128 * SPAD;
            float* Bb = BsBase + ((it + 1) & 1) * 128 * SPAD;
#pragma unroll
            for (int i = 0; i < 4; i++) {
                int r = lr + i * 32;
                cpa16(&Ab[r * SPAD + lc], A + (size_t)(m0 + r) * IN_DIM + k0 + lc, 16);
                cpa16(&Bb[r * SPAD + lc], W + (size_t)(n0 + r) * IN_DIM + k0 + lc, 16);
            }
            cpa_commit();
        }

        const float* Ab = AsBase + (it & 1) * 128 * SPAD;
        const float* Bb = BsBase + (it & 1) * 128 * SPAD;

#pragma unroll
        for (int kk = 0; kk < G1_BK; kk += 8) {
            uint32_t af[4][4], bf[4][2];
#pragma unroll
            for (int ms = 0; ms < 4; ms++) {
                int r  = wm + ms * 16 + (lane >> 2);
                int cA = kk + (lane & 3);
                af[ms][0] = __float_as_uint(Ab[r * SPAD + cA]);
                af[ms][1] = __float_as_uint(Ab[(r + 8) * SPAD + cA]);
                af[ms][2] = __float_as_uint(Ab[r * SPAD + cA + 4]);
                af[ms][3] = __float_as_uint(Ab[(r + 8) * SPAD + cA + 4]);
            }
#pragma unroll
            for (int ns = 0; ns < 4; ns++) {
                int n  = wn + ns * 8 + (lane >> 2);
                int ck = kk + (lane & 3);
                bf[ns][0] = __float_as_uint(Bb[n * SPAD + ck]);
                bf[ns][1] = __float_as_uint(Bb[n * SPAD + ck + 4]);
            }
#pragma unroll
            for (int ms = 0; ms < 4; ms++)
#pragma unroll
                for (int ns = 0; ns < 4; ns++)
                    mma_tf32(acc[ms][ns], af[ms], bf[ns]);
        }
        __syncthreads();
    }

    // epilogue: + bias (round to tf32 only for the p path, which feeds GEMM2)
#pragma unroll
    for (int ns = 0; ns < 4; ns++) {
        int c0 = n0 + wn + ns * 8 + 2 * (lane & 3);
        float b0v = bias[c0];
        float b1v = bias[c0 + 1];
#pragma unroll
        for (int ms = 0; ms < 4; ms++) {
            int r0 = m0 + wm + ms * 16 + (lane >> 2);
            float2 lo = make_float2(acc[ms][ns][0] + b0v, acc[ms][ns][1] + b1v);
            float2 hi = make_float2(acc[ms][ns][2] + b0v, acc[ms][ns][3] + b1v);
            if (roundOut) {
                lo.x = f2tf32f(lo.x); lo.y = f2tf32f(lo.y);
                hi.x = f2tf32f(hi.x); hi.y = f2tf32f(hi.y);
            }
            *(float2*)(out + (size_t)r0 * DIM + c0)       = lo;
            *(float2*)(out + (size_t)(r0 + 8) * DIM + c0) = hi;
        }
    }
}

// ---------------- grouped transform: p_t[b,i] = sum_j Wt[a_b][i][j] * p_embed[b][j] ----------------
// 4-stage cp.async ring to keep 2-3 W stages (32-48 KB) in flight per block.
#define T_BM 32
#define T_BN 128
#define T_BK 32
#define T_NS 4
#define T_SMEM ((T_NS * T_BM * SPAD + T_NS * T_BN * SPAD) * 4)   // 92160 B

__global__ __launch_bounds__(256) void trans_gemm(const float* __restrict__ Wt,
                                                  float* __restrict__ out)
{
    const int a     = blockIdx.y;
    const int cnt   = g_counts[a];
    const int chunk = blockIdx.z;
    if (chunk * T_BM >= cnt) return;

    const int start  = g_cursor[a] - cnt + chunk * T_BM;
    const int nvalid = min(T_BM, cnt - chunk * T_BM);

    __shared__ int s_ord[T_BM];
    extern __shared__ float tsm[];
    float* As = tsm;                       // [4][32][SPAD]
    float* Bs = tsm + T_NS * T_BM * SPAD;  // [4][128][SPAD]

    const int tid  = threadIdx.x;
    const int lane = tid & 31;
    const int warp = tid >> 5;
    const int wm = (warp >> 2) * 16;   // 2 warp-rows over 32 batches
    const int wn = (warp & 3) * 32;    // 4 warp-cols over 128 dims
    const int i0 = blockIdx.x * T_BN;

    if (tid < T_BM) s_ord[tid] = (tid < nvalid) ? g_order[start + tid] : -1;
    __syncthreads();

    const float* Wa = Wt + (size_t)a * DIM * DIM;

    const int lrA = tid >> 3;          // 0..31
    const int lc  = (tid & 7) * 4;
    const int bA  = s_ord[lrA];
    const float* srcA0 = (bA >= 0) ? g_pembed + (size_t)bA * DIM + lc : g_pembed;
    const uint32_t szA = (bA >= 0) ? 16u : 0u;

    float acc[4][4];
#pragma unroll
    for (int j = 0; j < 4; j++)
#pragma unroll
        for (int r = 0; r < 4; r++) acc[j][r] = 0.f;

    const int NITER = DIM / T_BK;      // 32

    // prologue: stages 0..2
#pragma unroll
    for (int st = 0; st < T_NS - 1; ++st) {
        const int k0 = st * T_BK;
        cpa16(&As[st * T_BM * SPAD + lrA * SPAD + lc], srcA0 + (szA ? k0 : 0), szA);
#pragma unroll
        for (int i = 0; i < 4; i++) {
            int r = lrA + i * 32;
            cpa16(&Bs[st * T_BN * SPAD + r * SPAD + lc],
                  Wa + (size_t)(i0 + r) * DIM + k0 + lc, 16);
        }
        cpa_commit();
    }

    for (int it = 0; it < NITER; ++it) {
        cpa_wait2();                   // stage `it` guaranteed complete
        __syncthreads();

        if (it + T_NS - 1 < NITER) {
            const int st = it + T_NS - 1;
            const int slot = st & (T_NS - 1);
            const int k0 = st * T_BK;
            cpa16(&As[slot * T_BM * SPAD + lrA * SPAD + lc], srcA0 + (szA ? k0 : 0), szA);
#pragma unroll
            for (int i = 0; i < 4; i++) {
                int r = lrA + i * 32;
                cpa16(&Bs[slot * T_BN * SPAD + r * SPAD + lc],
                      Wa + (size_t)(i0 + r) * DIM + k0 + lc, 16);
            }
            cpa_commit();
        } else {
            cpa_commit();              // empty group keeps wait_group bookkeeping correct
        }

        const int buf = it & (T_NS - 1);
        const float* Ab = As + buf * T_BM * SPAD;
        const float* Bb = Bs + buf * T_BN * SPAD;

#pragma unroll
        for (int kk = 0; kk < T_BK; kk += 8) {
            uint32_t af[4], bf[4][2];
            {
                int r  = wm + (lane >> 2);
                int cA = kk + (lane & 3);
                af[0] = __float_as_uint(Ab[r * SPAD + cA]);        // pre-rounded
                af[1] = __float_as_uint(Ab[(r + 8) * SPAD + cA]);
                af[2] = __float_as_uint(Ab[r * SPAD + cA + 4]);
                af[3] = __float_as_uint(Ab[(r + 8) * SPAD + cA + 4]);
            }
#pragma unroll
            for (int ns = 0; ns < 4; ns++) {
                int n  = wn + ns * 8 + (lane >> 2);
                int ck = kk + (lane & 3);
                bf[ns][0] = f2tf32(Bb[n * SPAD + ck]);             // W_trans: cvt here
                bf[ns][1] = f2tf32(Bb[n * SPAD + ck + 4]);
            }
#pragma unroll
            for (int ns = 0; ns < 4; ns++)
                mma_tf32(acc[ns], af, bf[ns]);
        }
        __syncthreads();
    }

    // epilogue: scatter to out[b*DIM + i]
    const int rA = wm + (lane >> 2);
    const int b0 = s_ord[rA];
    const int b1 = s_ord[rA + 8];
#pragma unroll
    for (int ns = 0; ns < 4; ns++) {
        int c0 = i0 + wn + ns * 8 + 2 * (lane & 3);
        if (b0 >= 0)
            *(float2*)(out + (size_t)b0 * DIM + c0) = make_float2(acc[ns][0], acc[ns][1]);
        if (b1 >= 0)
            *(float2*)(out + (size_t)b1 * DIM + c0) = make_float2(acc[ns][2], acc[ns][3]);
    }
}

// ---------------- launch ----------------
extern "C" void kernel_launch(void* const* d_in, const int* in_sizes, int n_in,
                              void* d_out, int out_size)
{
    const float* pre = (const float*)d_in[0];
    const float* eff = (const float*)d_in[1];
    const int*   act = (const int*)d_in[2];
    const float* Wp  = (const float*)d_in[3];
    const float* bp  = (const float*)d_in[4];
    const float* We  = (const float*)d_in[5];
    const float* be  = (const float*)d_in[6];
    const float* Wt  = (const float*)d_in[7];

    float* out   = (float*)d_out;              // p_transformed: (B,1,DIM,1)
    float* out_e = out + (size_t)B_SZ * DIM;   // e_embed: (B,DIM)

    cudaFuncSetAttribute(embed_gemm, cudaFuncAttributeMaxDynamicSharedMemorySize, G1_SMEM);
    cudaFuncSetAttribute(trans_gemm, cudaFuncAttributeMaxDynamicSharedMemorySize, T_SMEM);

    group_k<<<1, B_SZ>>>(act);

    wconv_k<<<2 * DIM * IN_DIM / 4 / 256, 256>>>(Wp, We);

    mean_kernel<<<dim3(B_SZ * IN_DIM / 4 / 256, 2), 256>>>(pre, eff);

    embed_gemm<<<dim3(DIM / G1_BN, DIM / G1_BM, 2), 256, G1_SMEM>>>(bp, be, out_e);

    trans_gemm<<<dim3(DIM / T_BN, NACT, B_SZ / T_BM), 256, T_SMEM>>>(Wt, out);
}